// round 1
// baseline (speedup 1.0000x reference)
#include <cuda_runtime.h>
#include <cstdint>

// ---------------------------------------------------------------------------
// SCAConv: out[b,o,l] = bias[o]
//                     + sum_i xu[b,i,l]*kernel[o,i]
//                     + sum_i xu[b,i,l]*b2[(l&31)*144+i]
//                     + sum_j H[o*128+(l>>5), j] * G[b,l,j]
// G[b,l,j] = sum_i xu[b,i,l]*W2[((l&31)*144+i)*32 + j]
// H[p,j]   = relu(b1[j] + sum_k W1[j,k]*inp(p,k)),
// inp(p)   = [ (p>>6)/64, 1-(p>>6)/64, (p&63)/64, 1-(p&63)/64, c_param[0..7] ]
// (p/r mapping reproduces the reference's reshape scramble exactly)
// ---------------------------------------------------------------------------

#define XS_BSTR 1732                    // per-batch stride (48*36 + 4 pad -> bank spread)
#define XS_OFF 0
#define XS_SIZE (8*XS_BSTR)             // 13856
#define KT_OFF (XS_OFF + XS_SIZE)
#define KT_SIZE (144*32)                // 4608
#define HS_OFF (KT_OFF + KT_SIZE)
#define HS_SIZE (32*32)                 // 1024
#define BIAS_OFF (HS_OFF + HS_SIZE)
#define BIAS_SIZE 32
#define W2S_OFF (BIAS_OFF + BIAS_SIZE)
#define W2S_HALF 9216                   // 2 lm * 144 * 32 floats per buffer
#define W2S_SIZE (2*W2S_HALF)
#define B2S_OFF (W2S_OFF + W2S_SIZE)
#define B2S_HALF 288
#define B2S_SIZE (2*B2S_HALF)
#define CS_OFF (B2S_OFF + B2S_SIZE)
#define CS_BSTR 2180                    // 32*68 + 4 pad
#define CS_LSTR 68
#define CS_SIZE (8*CS_BSTR)             // 17440
#define SMEM_FLOATS (CS_OFF + CS_SIZE)  // 55968 floats = 223872 B

__device__ __forceinline__ uint32_t smem_u32(const void* p) {
    return (uint32_t)__cvta_generic_to_shared(p);
}
__device__ __forceinline__ void cp_async16(uint32_t s, const void* g) {
    asm volatile("cp.async.cg.shared.global [%0], [%1], 16;\n" :: "r"(s), "l"(g));
}

__global__ __launch_bounds__(256, 1)
void sca_kernel(const float* __restrict__ x, const float* __restrict__ kern,
                const float* __restrict__ bias, const float* __restrict__ cpar,
                const float* __restrict__ W1, const float* __restrict__ b1,
                const float* __restrict__ W2, const float* __restrict__ b2,
                float* __restrict__ out)
{
    extern __shared__ float sm[];
    const int tid = threadIdx.x;
    const int lh = blockIdx.x;          // 0..127, covers l in [lh*32, lh*32+32)
    const int R  = lh >> 1;             // output row
    const int C0 = (lh & 1) * 32;       // output col base

    float* xs  = sm + XS_OFF;
    float* kT  = sm + KT_OFF;
    float* Hs  = sm + HS_OFF;
    float* bs  = sm + BIAS_OFF;
    float* W2s = sm + W2S_OFF;
    float* b2s = sm + B2S_OFF;
    float* Cs  = sm + CS_OFF;

    // ---------------- setup ----------------
    // x patch: rows R-1..R+1, cols C0-1..C0+32 (34), zero-padded at borders
    for (int idx = tid; idx < 8*16*3*34; idx += 256) {
        int cc = idx % 34;
        int t2 = idx / 34;
        int kr = t2 % 3; t2 /= 3;
        int c  = t2 % 16;
        int b  = t2 / 16;
        int r   = R - 1 + kr;
        int col = C0 - 1 + cc;
        float v = 0.f;
        if (r >= 0 && r < 64 && col >= 0 && col < 64)
            v = x[((b*16 + c)*64 + r)*64 + col];
        xs[b*XS_BSTR + (c*3 + kr)*36 + cc] = v;
    }
    // kernel transpose: kT[i][o]
    for (int idx = tid; idx < 4608; idx += 256) {
        int i = idx >> 5, o = idx & 31;
        kT[idx] = kern[o*144 + i];
    }
    // H rows for p = o*128 + lh (thread: o = tid>>3, j-quad = tid&7)
    {
        int o = tid >> 3, jq = tid & 7;
        int p = o*128 + lh;
        float inp[12];
        inp[0] = (float)(p >> 6) * (1.f/64.f);
        inp[1] = 1.f - inp[0];
        inp[2] = (float)(p & 63) * (1.f/64.f);
        inp[3] = 1.f - inp[2];
        #pragma unroll
        for (int k = 0; k < 8; k++) inp[4+k] = cpar[k];
        #pragma unroll
        for (int jj = 0; jj < 4; jj++) {
            int j = jq*4 + jj;
            float s = b1[j];
            #pragma unroll
            for (int k = 0; k < 12; k++) s += W1[j*12 + k] * inp[k];
            Hs[o*32 + j] = fmaxf(s, 0.f);
        }
    }
    if (tid < 32) bs[tid] = bias[tid];

    // prologue: async load pass 0 (W2 slice for lm 0..1 + b2 slice) into buf 0
    for (int idx = tid; idx < 2304; idx += 256)
        cp_async16(smem_u32(W2s + idx*4), W2 + idx*4);
    if (tid < 72)
        cp_async16(smem_u32(b2s + tid*4), b2 + tid*4);
    asm volatile("cp.async.commit_group;\n");

    __syncthreads();

    const int b   = tid & 7;     // batch
    const int cg  = tid >> 3;    // column group 0..31
    const int lmq = cg >> 4;     // which of 2 lm this pass
    const int rem = cg & 15;     // 0..7: G (j), 8..15: conv (o)
    const float* xub = xs + b*XS_BSTR;

    // ---------------- main loop: 16 passes x 2 lm ----------------
    for (int pass = 0; pass < 16; pass++) {
        int buf = pass & 1;
        if (pass < 15) {
            const float* src = W2 + (pass+1)*9216;
            float* dst = W2s + (buf^1)*W2S_HALF;
            for (int idx = tid; idx < 2304; idx += 256)
                cp_async16(smem_u32(dst + idx*4), src + idx*4);
            if (tid < 72)
                cp_async16(smem_u32(b2s + (buf^1)*B2S_HALF + tid*4),
                           b2 + (pass+1)*288 + tid*4);
            asm volatile("cp.async.commit_group;\n");
            asm volatile("cp.async.wait_group 1;\n");
        } else {
            asm volatile("cp.async.wait_group 0;\n");
        }
        __syncthreads();

        const int lm = pass*2 + lmq;
        const float4* wp;
        if (rem < 8) wp = (const float4*)(W2s + buf*W2S_HALF + lmq*4608 + rem*4);
        else         wp = (const float4*)(kT + (rem-8)*4);
        const float* b2p = b2s + buf*B2S_HALF + lmq*144;

        float4 acc = make_float4(0.f, 0.f, 0.f, 0.f);
        float tacc = 0.f;

        #pragma unroll
        for (int c = 0; c < 16; c++) {
            #pragma unroll
            for (int kr = 0; kr < 3; kr++) {
                const float* xrow = xub + (c*3 + kr)*36 + lm;
                #pragma unroll
                for (int kc = 0; kc < 3; kc++) {
                    const int i = c*9 + kr*3 + kc;
                    float xv = xrow[kc];
                    float4 w = wp[i*8];   // stride 32 floats
                    acc.x += xv * w.x; acc.y += xv * w.y;
                    acc.z += xv * w.z; acc.w += xv * w.w;
                    if (rem == 0) tacc += xv * b2p[i];
                }
            }
        }

        float* cbase = Cs + b*CS_BSTR + lm*CS_LSTR;
        int n = (rem < 8) ? rem*4 : 32 + (rem-8)*4;
        *(float4*)(cbase + n) = acc;
        if (rem == 0) cbase[64] = tacc;
        __syncthreads();   // protects W2s buf reuse by next pass's cp.async
    }

    // ---------------- phase 2: out = bias + t + conv + H·G ----------------
    {
        int bb = tid >> 5, lm = tid & 31;
        const float* cb = Cs + bb*CS_BSTR + lm*CS_LSTR;
        float g[32];
        #pragma unroll
        for (int q = 0; q < 8; q++) {
            float4 v = *(const float4*)(cb + q*4);
            g[q*4+0] = v.x; g[q*4+1] = v.y; g[q*4+2] = v.z; g[q*4+3] = v.w;
        }
        float tv = cb[64];
        float* ob = out + bb*(32*4096) + lh*32 + lm;
        #pragma unroll
        for (int o = 0; o < 32; o++) {
            float s = bs[o] + tv + cb[32+o];
            const float* hrow = Hs + o*32;
            #pragma unroll
            for (int j = 0; j < 32; j++) s += hrow[j] * g[j];
            ob[o*4096] = s;   // coalesced: lanes = consecutive lm
        }
    }
}

extern "C" void kernel_launch(void* const* d_in, const int* in_sizes, int n_in,
                              void* d_out, int out_size)
{
    const float* x    = (const float*)d_in[0];   // (8,16,64,64)
    const float* kern = (const float*)d_in[1];   // (32,144)
    const float* bias = (const float*)d_in[2];   // (32,)
    const float* cpar = (const float*)d_in[3];   // (1,8)
    const float* W1   = (const float*)d_in[4];   // (32,12)
    const float* b1   = (const float*)d_in[5];   // (32,)
    const float* W2   = (const float*)d_in[6];   // (4608,32)
    const float* b2   = (const float*)d_in[7];   // (4608,)
    float* out = (float*)d_out;                  // (8,32,64,64)

    cudaFuncSetAttribute(sca_kernel, cudaFuncAttributeMaxDynamicSharedMemorySize,
                         SMEM_FLOATS * 4);
    sca_kernel<<<128, 256, SMEM_FLOATS * 4>>>(x, kern, bias, cpar, W1, b1, W2, b2, out);
}

// round 2
// speedup vs baseline: 1.0205x; 1.0205x over previous
#include <cuda_runtime.h>
#include <cstdint>

// ---------------------------------------------------------------------------
// SCAConv: out[b,o,l] = bias[o]
//                     + sum_i xu[b,i,l]*kernel[o,i]
//                     + sum_i xu[b,i,l]*b2[(l&31)*144+i]
//                     + sum_j H[o*128+(l>>5), j] * G[b,l,j]
// G[b,l,j] = sum_i xu[b,i,l]*W2[((l&31)*144+i)*32 + j]
// H[p,j]   = relu(b1[j] + sum_k W1[j,k]*inp(p,k)),
// inp(p)   = [ (p>>6)/64, 1-(p>>6)/64, (p&63)/64, 1-(p&63)/64, c_param[0..7] ]
// (p/r mapping reproduces the reference's reshape scramble exactly)
// ---------------------------------------------------------------------------

#define XS_BSTR 1732                    // per-batch stride (48*36 + 4 pad -> bank spread)
#define XS_OFF 0
#define XS_SIZE (8*XS_BSTR)             // 13856
#define KT_OFF (XS_OFF + XS_SIZE)
#define KT_SIZE (144*32)                // 4608
#define HS_OFF (KT_OFF + KT_SIZE)
#define HS_SIZE (32*32)                 // 1024
#define BIAS_OFF (HS_OFF + HS_SIZE)
#define BIAS_SIZE 32
#define W2S_OFF (BIAS_OFF + BIAS_SIZE)
#define W2S_HALF 9216                   // 2 lm * 144 * 32 floats per buffer
#define W2S_SIZE (2*W2S_HALF)
#define B2S_OFF (W2S_OFF + W2S_SIZE)
#define B2S_HALF 288
#define B2S_SIZE (2*B2S_HALF)
#define CS_OFF (B2S_OFF + B2S_SIZE)
#define CS_BSTR 2180                    // 32*68 + 4 pad
#define CS_LSTR 68
#define CS_SIZE (8*CS_BSTR)             // 17440
#define SMEM_FLOATS (CS_OFF + CS_SIZE)  // 55968 floats = 223872 B

__device__ __forceinline__ uint32_t smem_u32(const void* p) {
    return (uint32_t)__cvta_generic_to_shared(p);
}
__device__ __forceinline__ void cp_async16(uint32_t s, const void* g) {
    asm volatile("cp.async.cg.shared.global [%0], [%1], 16;\n" :: "r"(s), "l"(g));
}

__global__ __launch_bounds__(256, 1)
void sca_kernel(const float* __restrict__ x, const float* __restrict__ kern,
                const float* __restrict__ bias, const float* __restrict__ cpar,
                const float* __restrict__ W1, const float* __restrict__ b1,
                const float* __restrict__ W2, const float* __restrict__ b2,
                float* __restrict__ out)
{
    extern __shared__ float sm[];
    const int tid = threadIdx.x;
    const int lh = blockIdx.x;          // 0..127, covers l in [lh*32, lh*32+32)
    const int R  = lh >> 1;             // output row
    const int C0 = (lh & 1) * 32;       // output col base

    float* xs  = sm + XS_OFF;
    float* kT  = sm + KT_OFF;
    float* Hs  = sm + HS_OFF;
    float* bs  = sm + BIAS_OFF;
    float* W2s = sm + W2S_OFF;
    float* b2s = sm + B2S_OFF;
    float* Cs  = sm + CS_OFF;

    // ---------------- setup ----------------
    // x patch: rows R-1..R+1, cols C0-1..C0+32 (34), zero-padded at borders
    for (int idx = tid; idx < 8*16*3*34; idx += 256) {
        int cc = idx % 34;
        int t2 = idx / 34;
        int kr = t2 % 3; t2 /= 3;
        int c  = t2 % 16;
        int b  = t2 / 16;
        int r   = R - 1 + kr;
        int col = C0 - 1 + cc;
        float v = 0.f;
        if (r >= 0 && r < 64 && col >= 0 && col < 64)
            v = x[((b*16 + c)*64 + r)*64 + col];
        xs[b*XS_BSTR + (c*3 + kr)*36 + cc] = v;
    }
    // kernel transpose: kT[i][o]
    for (int idx = tid; idx < 4608; idx += 256) {
        int i = idx >> 5, o = idx & 31;
        kT[idx] = kern[o*144 + i];
    }
    // H rows for p = o*128 + lh (thread: o = tid>>3, j-quad = tid&7)
    {
        int o = tid >> 3, jq = tid & 7;
        int p = o*128 + lh;
        float inp[12];
        inp[0] = (float)(p >> 6) * (1.f/64.f);
        inp[1] = 1.f - inp[0];
        inp[2] = (float)(p & 63) * (1.f/64.f);
        inp[3] = 1.f - inp[2];
        #pragma unroll
        for (int k = 0; k < 8; k++) inp[4+k] = cpar[k];
        #pragma unroll
        for (int jj = 0; jj < 4; jj++) {
            int j = jq*4 + jj;
            float s = b1[j];
            #pragma unroll
            for (int k = 0; k < 12; k++) s += W1[j*12 + k] * inp[k];
            Hs[o*32 + j] = fmaxf(s, 0.f);
        }
    }
    if (tid < 32) bs[tid] = bias[tid];

    // prologue: async load pass 0 (W2 slice for lm 0..1 + b2 slice) into buf 0
    for (int idx = tid; idx < 2304; idx += 256)
        cp_async16(smem_u32(W2s + idx*4), W2 + idx*4);
    if (tid < 72)
        cp_async16(smem_u32(b2s + tid*4), b2 + tid*4);
    asm volatile("cp.async.commit_group;\n");

    __syncthreads();

    const int b   = tid & 7;     // batch
    const int cg  = tid >> 3;    // column group 0..31
    const int lmq = cg >> 4;     // which of 2 lm this pass
    const int rem = cg & 15;     // 0..7: G (j), 8..15: conv (o)
    const float* xub = xs + b*XS_BSTR;

    // ---------------- main loop: 16 passes x 2 lm ----------------
    for (int pass = 0; pass < 16; pass++) {
        int buf = pass & 1;
        if (pass < 15) {
            const float* src = W2 + (pass+1)*9216;
            float* dst = W2s + (buf^1)*W2S_HALF;
            for (int idx = tid; idx < 2304; idx += 256)
                cp_async16(smem_u32(dst + idx*4), src + idx*4);
            if (tid < 72)
                cp_async16(smem_u32(b2s + (buf^1)*B2S_HALF + tid*4),
                           b2 + (pass+1)*288 + tid*4);
            asm volatile("cp.async.commit_group;\n");
            asm volatile("cp.async.wait_group 1;\n");
        } else {
            asm volatile("cp.async.wait_group 0;\n");
        }
        __syncthreads();

        const int lm = pass*2 + lmq;
        const float4* wp;
        if (rem < 8) wp = (const float4*)(W2s + buf*W2S_HALF + lmq*4608 + rem*4);
        else         wp = (const float4*)(kT + (rem-8)*4);
        const float* b2p = b2s + buf*B2S_HALF + lmq*144;

        float4 acc = make_float4(0.f, 0.f, 0.f, 0.f);
        float tacc = 0.f;

        #pragma unroll
        for (int c = 0; c < 16; c++) {
            #pragma unroll
            for (int kr = 0; kr < 3; kr++) {
                const float* xrow = xub + (c*3 + kr)*36 + lm;
                #pragma unroll
                for (int kc = 0; kc < 3; kc++) {
                    const int i = c*9 + kr*3 + kc;
                    float xv = xrow[kc];
                    float4 w = wp[i*8];   // stride 32 floats
                    acc.x += xv * w.x; acc.y += xv * w.y;
                    acc.z += xv * w.z; acc.w += xv * w.w;
                    if (rem == 0) tacc += xv * b2p[i];
                }
            }
        }

        float* cbase = Cs + b*CS_BSTR + lm*CS_LSTR;
        int n = (rem < 8) ? rem*4 : 32 + (rem-8)*4;
        *(float4*)(cbase + n) = acc;
        if (rem == 0) cbase[64] = tacc;
        __syncthreads();   // protects W2s buf reuse by next pass's cp.async
    }

    // ---------------- phase 2: out = bias + t + conv + H·G ----------------
    {
        int bb = tid >> 5, lm = tid & 31;
        const float* cb = Cs + bb*CS_BSTR + lm*CS_LSTR;
        float g[32];
        #pragma unroll
        for (int q = 0; q < 8; q++) {
            float4 v = *(const float4*)(cb + q*4);
            g[q*4+0] = v.x; g[q*4+1] = v.y; g[q*4+2] = v.z; g[q*4+3] = v.w;
        }
        float tv = cb[64];
        float* ob = out + bb*(32*4096) + lh*32 + lm;
        #pragma unroll
        for (int o = 0; o < 32; o++) {
            float s = bs[o] + tv + cb[32+o];
            const float* hrow = Hs + o*32;
            #pragma unroll
            for (int j = 0; j < 32; j++) s += hrow[j] * g[j];
            ob[o*4096] = s;   // coalesced: lanes = consecutive lm
        }
    }
}

extern "C" void kernel_launch(void* const* d_in, const int* in_sizes, int n_in,
                              void* d_out, int out_size)
{
    const float* x    = (const float*)d_in[0];   // (8,16,64,64)
    const float* kern = (const float*)d_in[1];   // (32,144)
    const float* bias = (const float*)d_in[2];   // (32,)
    const float* cpar = (const float*)d_in[3];   // (1,8)
    const float* W1   = (const float*)d_in[4];   // (32,12)
    const float* b1   = (const float*)d_in[5];   // (32,)
    const float* W2   = (const float*)d_in[6];   // (4608,32)
    const float* b2   = (const float*)d_in[7];   // (4608,)
    float* out = (float*)d_out;                  // (8,32,64,64)

    cudaFuncSetAttribute(sca_kernel, cudaFuncAttributeMaxDynamicSharedMemorySize,
                         SMEM_FLOATS * 4);
    sca_kernel<<<128, 256, SMEM_FLOATS * 4>>>(x, kern, bias, cpar, W1, b1, W2, b2, out);
}

// round 3
// speedup vs baseline: 1.8645x; 1.8271x over previous
#include <cuda_runtime.h>
#include <cstdint>

// ---------------------------------------------------------------------------
// SCAConv decomposition (identical math to the passing R1 kernel):
// out[b,o,l] = bias[o] + sum_i xu*kernel[o,i] + sum_i xu*b2[(l&31)*144+i]
//            + sum_j H[o*128+(l>>5), j] * G[b,l,j]
// G[b,l,j] = sum_i xu[b,i,l] * W2[((l&31)*144+i)*32 + j]
//
// New structure: 512 threads, register tiles of 4 batches x 8 columns,
// x-patch batch-innermost in smem (1 LDS.128 = 4 batches), weights streamed
// by LDG.128 from L2 (W2) / L1 (transposed conv kernel). No mainloop syncs.
// ---------------------------------------------------------------------------

#define XS_OFF   0
#define XS_RSTR  35                    // col stride per (c,kr) row, 34 used + 1 pad
#define XS_SIZE  (48*XS_RSTR*8)        // 13440 floats (batch innermost, 8 wide)
#define HS_OFF   (XS_OFF + XS_SIZE)
#define HS_SIZE  (32*32)
#define BIAS_OFF (HS_OFF + HS_SIZE)
#define BIAS_SIZE 32
#define CS_OFF   (BIAS_OFF + BIAS_SIZE)
#define CS_LSTR  68                    // per-lm: 32 G + 32 conv + 1 t + 3 pad
#define CS_BSTR  (32*CS_LSTR)
#define CS_SIZE  (8*CS_BSTR)           // 17408
#define SMEM_FLOATS (CS_OFF + CS_SIZE) // 31904 floats = 127.6 KB

__device__ float g_kT[144*32];         // kernel transposed: kT[i][o]

__global__ void prep_kernel(const float* __restrict__ kern) {
    int idx = blockIdx.x * 256 + threadIdx.x;
    if (idx < 4608) {
        int i = idx >> 5, o = idx & 31;
        g_kT[idx] = kern[o*144 + i];
    }
}

__global__ __launch_bounds__(512, 1)
void sca_kernel(const float* __restrict__ x, const float* __restrict__ bias,
                const float* __restrict__ cpar,
                const float* __restrict__ W1, const float* __restrict__ b1,
                const float* __restrict__ W2, const float* __restrict__ b2,
                float* __restrict__ out)
{
    extern __shared__ float sm[];
    float* xs = sm + XS_OFF;
    float* Hs = sm + HS_OFF;
    float* bs = sm + BIAS_OFF;
    float* Cs = sm + CS_OFF;

    const int tid = threadIdx.x;
    const int lh  = blockIdx.x;        // covers l in [lh*32, lh*32+32)
    const int R   = lh >> 1;
    const int C0  = (lh & 1) * 32;

    // ---------- setup: x patch, batch-innermost ----------
    // xs[((c*3+kr)*35 + cc)*8 + b] = x[b][c][R-1+kr][C0-1+cc], zero padded
    for (int idx = tid; idx < 8*16*3*34; idx += 512) {
        int cc = idx % 34;
        int t2 = idx / 34;
        int kr = t2 % 3;  t2 /= 3;
        int c  = t2 % 16;
        int b  = t2 / 16;
        int r   = R - 1 + kr;
        int col = C0 - 1 + cc;
        float v = 0.f;
        if (r >= 0 && r < 64 && col >= 0 && col < 64)
            v = x[((b*16 + c)*64 + r)*64 + col];
        xs[((c*3 + kr)*XS_RSTR + cc)*8 + b] = v;
    }

    // ---------- H rows: H[o*128+lh][j], thread (o, j-pair) ----------
    {
        int o  = tid >> 4;             // 0..31
        int jh = tid & 15;             // 2 j per thread
        int p  = o*128 + lh;
        float inp[12];
        inp[0] = (float)(p >> 6) * (1.f/64.f);
        inp[1] = 1.f - inp[0];
        inp[2] = (float)(p & 63) * (1.f/64.f);
        inp[3] = 1.f - inp[2];
        #pragma unroll
        for (int k = 0; k < 8; k++) inp[4+k] = cpar[k];
        #pragma unroll
        for (int jj = 0; jj < 2; jj++) {
            int j = jh*2 + jj;
            float s = b1[j];
            #pragma unroll
            for (int k = 0; k < 12; k++) s += W1[j*12 + k] * inp[k];
            Hs[o*32 + j] = fmaxf(s, 0.f);
        }
    }
    if (tid < 32) bs[tid] = bias[tid];
    __syncthreads();

    // ---------- main loop: register tile 4b x 8cols, no syncs ----------
    // tid = part*256 + lm*8 + bg*4 + cg
    //   part 0: G columns j = cg*8..cg*8+7   (weights = W2, L2-hot)
    //   part 1: conv columns o = cg*8..+7    (weights = g_kT, L1-hot)
    {
        const int part = tid >> 8;
        const int t    = tid & 255;
        const int lm   = t >> 3;
        const int bg   = (t >> 2) & 1;
        const int cg   = t & 3;

        const float* wp = part ? (g_kT + cg*8) : (W2 + lm*4608 + cg*8);
        const float* xp = xs + lm*8 + bg*4;

        float acc[4][8];
        #pragma unroll
        for (int bi = 0; bi < 4; bi++)
            #pragma unroll
            for (int n = 0; n < 8; n++) acc[bi][n] = 0.f;

        for (int c = 0; c < 16; ++c) {
            const float* xrow = xp + c*(3*XS_RSTR*8);
            const float* wrow = wp + c*(9*32);
            #pragma unroll
            for (int kr = 0; kr < 3; ++kr) {
                #pragma unroll
                for (int kc = 0; kc < 3; ++kc) {
                    float4 xv = *(const float4*)(xrow + (kr*XS_RSTR + kc)*8);
                    const float* w = wrow + (kr*3 + kc)*32;
                    float4 w0 = *(const float4*)(w);
                    float4 w1 = *(const float4*)(w + 4);
                    float xa[4] = {xv.x, xv.y, xv.z, xv.w};
                    float wv[8] = {w0.x, w0.y, w0.z, w0.w,
                                   w1.x, w1.y, w1.z, w1.w};
                    #pragma unroll
                    for (int bi = 0; bi < 4; bi++)
                        #pragma unroll
                        for (int n = 0; n < 8; n++)
                            acc[bi][n] += xa[bi] * wv[n];
                }
            }
        }

        float* cb = Cs + (bg*4)*CS_BSTR + lm*CS_LSTR + part*32 + cg*8;
        #pragma unroll
        for (int bi = 0; bi < 4; bi++) {
            *(float4*)(cb + bi*CS_BSTR)     = make_float4(acc[bi][0], acc[bi][1], acc[bi][2], acc[bi][3]);
            *(float4*)(cb + bi*CS_BSTR + 4) = make_float4(acc[bi][4], acc[bi][5], acc[bi][6], acc[bi][7]);
        }
    }

    // ---------- t-term tail: tacc[b][lm] = sum_i xu * b2[lm*144+i] ----------
    if (tid < 64) {
        int lm2 = tid >> 1, bg2 = tid & 1;
        const float* xp2 = xs + lm2*8 + bg2*4;
        const float* bp2 = b2 + lm2*144;
        float t4[4] = {0.f, 0.f, 0.f, 0.f};
        for (int c = 0; c < 16; ++c) {
            #pragma unroll
            for (int kr = 0; kr < 3; ++kr) {
                #pragma unroll
                for (int kc = 0; kc < 3; ++kc) {
                    int i = c*9 + kr*3 + kc;
                    float4 xv = *(const float4*)(xp2 + (c*3*XS_RSTR + kr*XS_RSTR + kc)*8);
                    float bv = bp2[i];
                    t4[0] += xv.x * bv;  t4[1] += xv.y * bv;
                    t4[2] += xv.z * bv;  t4[3] += xv.w * bv;
                }
            }
        }
        #pragma unroll
        for (int bi = 0; bi < 4; bi++)
            Cs[(bg2*4 + bi)*CS_BSTR + lm2*CS_LSTR + 64] = t4[bi];
    }
    __syncthreads();

    // ---------- epilogue: out = bias + t + conv + H·G ----------
    {
        int b   = tid >> 6;            // 0..7
        int oh  = (tid >> 5) & 1;      // o half
        int lm3 = tid & 31;            // lanes = consecutive lm -> coalesced
        const float* cb = Cs + b*CS_BSTR + lm3*CS_LSTR;

        float g[32];
        #pragma unroll
        for (int q = 0; q < 8; q++) {
            float4 v = *(const float4*)(cb + q*4);
            g[q*4+0] = v.x; g[q*4+1] = v.y; g[q*4+2] = v.z; g[q*4+3] = v.w;
        }
        float cw[16];
        #pragma unroll
        for (int q = 0; q < 4; q++) {
            float4 v = *(const float4*)(cb + 32 + oh*16 + q*4);
            cw[q*4+0] = v.x; cw[q*4+1] = v.y; cw[q*4+2] = v.z; cw[q*4+3] = v.w;
        }
        float tv = cb[64];

        float* ob = out + b*(32*4096) + (oh*16)*4096 + lh*32 + lm3;
        #pragma unroll
        for (int oo = 0; oo < 16; oo++) {
            int o = oh*16 + oo;
            float s = bs[o] + tv + cw[oo];
            const float4* h4 = (const float4*)(Hs + o*32);
            #pragma unroll
            for (int q = 0; q < 8; q++) {
                float4 h = h4[q];
                s += h.x*g[q*4] + h.y*g[q*4+1] + h.z*g[q*4+2] + h.w*g[q*4+3];
            }
            ob[oo*4096] = s;
        }
    }
}

extern "C" void kernel_launch(void* const* d_in, const int* in_sizes, int n_in,
                              void* d_out, int out_size)
{
    const float* x    = (const float*)d_in[0];   // (8,16,64,64)
    const float* kern = (const float*)d_in[1];   // (32,144)
    const float* bias = (const float*)d_in[2];   // (32,)
    const float* cpar = (const float*)d_in[3];   // (1,8)
    const float* W1   = (const float*)d_in[4];   // (32,12)
    const float* b1   = (const float*)d_in[5];   // (32,)
    const float* W2   = (const float*)d_in[6];   // (4608,32)
    const float* b2   = (const float*)d_in[7];   // (4608,)
    float* out = (float*)d_out;                  // (8,32,64,64)

    prep_kernel<<<18, 256>>>(kern);
    cudaFuncSetAttribute(sca_kernel, cudaFuncAttributeMaxDynamicSharedMemorySize,
                         SMEM_FLOATS * 4);
    sca_kernel<<<128, 512, SMEM_FLOATS * 4>>>(x, bias, cpar, W1, b1, W2, b2, out);
}

// round 4
// speedup vs baseline: 1.8759x; 1.0061x over previous
#include <cuda_runtime.h>
#include <cstdint>

// ---------------------------------------------------------------------------
// SCAConv decomposition (same math as R2):
// out[b,o,l] = bias[o] + sum_i xu*kernel[o,i] + sum_i xu*b2[(l&31)*144+i]
//            + sum_j H[o*128+(l>>5), j] * G[b,l,j]
// G[b,l,j] = sum_i xu[b,i,l] * W2[((l&31)*144+i)*32 + j]
//
// R3: packed fma.rn.f32x2 over the batch dimension (x pairs come free from
// the batch-innermost smem layout), thread tile 8 batches x 4 columns so a
// warp reads each weight line exactly once (no bg duplication).
// ---------------------------------------------------------------------------

#define XS_OFF   0
#define XS_RSTR  35
#define XS_SIZE  (48*XS_RSTR*8)        // 13440 floats, batch innermost
#define HS_OFF   (XS_OFF + XS_SIZE)
#define HS_SIZE  (32*32)
#define BIAS_OFF (HS_OFF + HS_SIZE)
#define BIAS_SIZE 32
#define CS_OFF   (BIAS_OFF + BIAS_SIZE)
#define CS_LSTR  68                    // per-lm: 32 G + 32 conv + 1 t + 3 pad
#define CS_BSTR  (32*CS_LSTR)
#define CS_SIZE  (8*CS_BSTR)
#define SMEM_FLOATS (CS_OFF + CS_SIZE) // 31904 floats = 127.6 KB

__device__ float g_kT[144*32];         // kernel transposed: kT[i][o]

__global__ void prep_kernel(const float* __restrict__ kern) {
    int idx = blockIdx.x * 256 + threadIdx.x;
    if (idx < 4608) {
        int i = idx >> 5, o = idx & 31;
        g_kT[idx] = kern[o*144 + i];
    }
}

typedef unsigned long long ull;

#define PACK2(d, s)   asm("mov.b64 %0, {%1, %1};" : "=l"(d) : "f"(s))
#define UNPACK2(lo, hi, v) asm("mov.b64 {%0, %1}, %2;" : "=f"(lo), "=f"(hi) : "l"(v))
#define FMA2(acc, a, b) asm("fma.rn.f32x2 %0, %1, %2, %0;" : "+l"(acc) : "l"(a), "l"(b))

__global__ __launch_bounds__(512, 1)
void sca_kernel(const float* __restrict__ x, const float* __restrict__ bias,
                const float* __restrict__ cpar,
                const float* __restrict__ W1, const float* __restrict__ b1,
                const float* __restrict__ W2, const float* __restrict__ b2,
                float* __restrict__ out)
{
    extern __shared__ float sm[];
    float* xs = sm + XS_OFF;
    float* Hs = sm + HS_OFF;
    float* bs = sm + BIAS_OFF;
    float* Cs = sm + CS_OFF;

    const int tid = threadIdx.x;
    const int lh  = blockIdx.x;
    const int R   = lh >> 1;
    const int C0  = (lh & 1) * 32;

    // ---------- setup: x patch, batch-innermost ----------
    for (int idx = tid; idx < 8*16*3*34; idx += 512) {
        int cc = idx % 34;
        int t2 = idx / 34;
        int kr = t2 % 3;  t2 /= 3;
        int c  = t2 % 16;
        int b  = t2 / 16;
        int r   = R - 1 + kr;
        int col = C0 - 1 + cc;
        float v = 0.f;
        if (r >= 0 && r < 64 && col >= 0 && col < 64)
            v = x[((b*16 + c)*64 + r)*64 + col];
        xs[((c*3 + kr)*XS_RSTR + cc)*8 + b] = v;
    }

    // ---------- H rows ----------
    {
        int o  = tid >> 4;
        int jh = tid & 15;
        int p  = o*128 + lh;
        float inp[12];
        inp[0] = (float)(p >> 6) * (1.f/64.f);
        inp[1] = 1.f - inp[0];
        inp[2] = (float)(p & 63) * (1.f/64.f);
        inp[3] = 1.f - inp[2];
        #pragma unroll
        for (int k = 0; k < 8; k++) inp[4+k] = cpar[k];
        #pragma unroll
        for (int jj = 0; jj < 2; jj++) {
            int j = jh*2 + jj;
            float s = b1[j];
            #pragma unroll
            for (int k = 0; k < 12; k++) s += W1[j*12 + k] * inp[k];
            Hs[o*32 + j] = fmaxf(s, 0.f);
        }
    }
    if (tid < 32) bs[tid] = bias[tid];
    __syncthreads();

    // ---------- main loop: 8 batches x 4 cols per thread, f32x2 packed ----------
    // tid = part*256 + lm*8 + cg ; part 0: G cols j = cg*4..+3 (W2, L2-hot)
    //                              part 1: conv cols o = cg*4..+3 (g_kT, L1-hot)
    {
        const int part = tid >> 8;
        const int t    = tid & 255;
        const int lm   = t >> 3;
        const int cg   = t & 7;

        const float* wp = part ? (g_kT + cg*4) : (W2 + lm*4608 + cg*4);
        const float* xp = xs + lm*8;

        ull acc[4][4];   // [col n][batch pair bp]
        #pragma unroll
        for (int n = 0; n < 4; n++)
            #pragma unroll
            for (int bp = 0; bp < 4; bp++) acc[n][bp] = 0ull;

        for (int c = 0; c < 16; ++c) {
            const float* xc = xp + c*(3*XS_RSTR*8);
            const float* wc = wp + c*(9*32);
            #pragma unroll
            for (int kr = 0; kr < 3; ++kr) {
                #pragma unroll
                for (int kc = 0; kc < 3; ++kc) {
                    const float* xr = xc + (kr*XS_RSTR + kc)*8;
                    ulonglong2 xa = *(const ulonglong2*)(xr);      // b0..b3
                    ulonglong2 xb = *(const ulonglong2*)(xr + 4);  // b4..b7
                    float4 w = *(const float4*)(wc + (kr*3 + kc)*32);
                    ull wpk[4];
                    PACK2(wpk[0], w.x); PACK2(wpk[1], w.y);
                    PACK2(wpk[2], w.z); PACK2(wpk[3], w.w);
                    #pragma unroll
                    for (int n = 0; n < 4; n++) {
                        FMA2(acc[n][0], xa.x, wpk[n]);
                        FMA2(acc[n][1], xa.y, wpk[n]);
                        FMA2(acc[n][2], xb.x, wpk[n]);
                        FMA2(acc[n][3], xb.y, wpk[n]);
                    }
                }
            }
        }

        // unpack -> per-batch float4 stores
        float f[8][4];
        #pragma unroll
        for (int n = 0; n < 4; n++)
            #pragma unroll
            for (int bp = 0; bp < 4; bp++)
                UNPACK2(f[2*bp][n], f[2*bp+1][n], acc[n][bp]);
        float* cb = Cs + lm*CS_LSTR + part*32 + cg*4;
        #pragma unroll
        for (int b = 0; b < 8; b++)
            *(float4*)(cb + b*CS_BSTR) = make_float4(f[b][0], f[b][1], f[b][2], f[b][3]);
    }

    // ---------- t-term tail: t[b][lm] = sum_i xu * b2[lm*144+i] ----------
    if (tid < 32) {
        int lm2 = tid;
        const float* xp2 = xs + lm2*8;
        const float* bp2 = b2 + lm2*144;
        ull ta[4] = {0ull, 0ull, 0ull, 0ull};
        for (int c = 0; c < 16; ++c) {
            #pragma unroll
            for (int kr = 0; kr < 3; ++kr) {
                #pragma unroll
                for (int kc = 0; kc < 3; ++kc) {
                    const float* xr = xp2 + (c*3*XS_RSTR + kr*XS_RSTR + kc)*8;
                    ulonglong2 xa = *(const ulonglong2*)(xr);
                    ulonglong2 xb = *(const ulonglong2*)(xr + 4);
                    ull bv; PACK2(bv, bp2[c*9 + kr*3 + kc]);
                    FMA2(ta[0], xa.x, bv); FMA2(ta[1], xa.y, bv);
                    FMA2(ta[2], xb.x, bv); FMA2(ta[3], xb.y, bv);
                }
            }
        }
        #pragma unroll
        for (int bp = 0; bp < 4; bp++) {
            float lo, hi; UNPACK2(lo, hi, ta[bp]);
            Cs[(2*bp)*CS_BSTR   + lm2*CS_LSTR + 64] = lo;
            Cs[(2*bp+1)*CS_BSTR + lm2*CS_LSTR + 64] = hi;
        }
    }
    __syncthreads();

    // ---------- epilogue: out = bias + t + conv + H·G ----------
    {
        int b   = tid >> 6;
        int oh  = (tid >> 5) & 1;
        int lm3 = tid & 31;
        const float* cb = Cs + b*CS_BSTR + lm3*CS_LSTR;

        float g[32];
        #pragma unroll
        for (int q = 0; q < 8; q++) {
            float4 v = *(const float4*)(cb + q*4);
            g[q*4+0] = v.x; g[q*4+1] = v.y; g[q*4+2] = v.z; g[q*4+3] = v.w;
        }
        float cw[16];
        #pragma unroll
        for (int q = 0; q < 4; q++) {
            float4 v = *(const float4*)(cb + 32 + oh*16 + q*4);
            cw[q*4+0] = v.x; cw[q*4+1] = v.y; cw[q*4+2] = v.z; cw[q*4+3] = v.w;
        }
        float tv = cb[64];

        float* ob = out + b*(32*4096) + (oh*16)*4096 + lh*32 + lm3;
        #pragma unroll
        for (int oo = 0; oo < 16; oo++) {
            int o = oh*16 + oo;
            float s = bs[o] + tv + cw[oo];
            const float4* h4 = (const float4*)(Hs + o*32);
            #pragma unroll
            for (int q = 0; q < 8; q++) {
                float4 h = h4[q];
                s += h.x*g[q*4] + h.y*g[q*4+1] + h.z*g[q*4+2] + h.w*g[q*4+3];
            }
            ob[oo*4096] = s;
        }
    }
}

extern "C" void kernel_launch(void* const* d_in, const int* in_sizes, int n_in,
                              void* d_out, int out_size)
{
    const float* x    = (const float*)d_in[0];   // (8,16,64,64)
    const float* kern = (const float*)d_in[1];   // (32,144)
    const float* bias = (const float*)d_in[2];   // (32,)
    const float* cpar = (const float*)d_in[3];   // (1,8)
    const float* W1   = (const float*)d_in[4];   // (32,12)
    const float* b1   = (const float*)d_in[5];   // (32,)
    const float* W2   = (const float*)d_in[6];   // (4608,32)
    const float* b2   = (const float*)d_in[7];   // (4608,)
    float* out = (float*)d_out;                  // (8,32,64,64)

    prep_kernel<<<18, 256>>>(kern);
    cudaFuncSetAttribute(sca_kernel, cudaFuncAttributeMaxDynamicSharedMemorySize,
                         SMEM_FLOATS * 4);
    sca_kernel<<<128, 512, SMEM_FLOATS * 4>>>(x, bias, cpar, W1, b1, W2, b2, out);
}